// round 15
// baseline (speedup 1.0000x reference)
#include <cuda_runtime.h>
#include <cuda_bf16.h>
#include <cuda_fp16.h>
#include <cstdint>

// Problem constants
#define BATCH 128
#define NN    128
#define D_IN  6
#define D_MP  64
#define TOTAL (BATCH*NN)    // 16384
#define U_STRIDE 512
#define U_PER_B  (512*512)

__device__ __half g_A0h[TOTAL*128];         // fp16(h @ We0[:64])
__device__ __half g_B0h[TOTAL*128];         // fp16(h @ We0[64:] + be0)
__device__ __half g_Bhi[128*136];           // We1^T fp16, padded [n][136]
__device__ __half g_W2hi[16*136];           // We2^T fp16, padded [c][136]

__device__ __forceinline__ float lrelu(float v){ return v >= 0.f ? v : 0.1f*v; }

__device__ __forceinline__ uint32_t smem_u32(const void* p){
    uint32_t a;
    asm("{ .reg .u64 t; cvta.to.shared.u64 t, %1; cvt.u32.u64 %0, t; }"
        : "=r"(a) : "l"(p));
    return a;
}

#define LDM4(r, addr) \
    asm volatile("ldmatrix.sync.aligned.m8n8.x4.shared.b16 {%0,%1,%2,%3}, [%4];" \
        : "=r"((r)[0]), "=r"((r)[1]), "=r"((r)[2]), "=r"((r)[3]) : "r"(addr))

#define MMA16816H(d, a, b0_, b1_) \
    asm volatile("mma.sync.aligned.m16n8k16.row.col.f32.f16.f16.f32 " \
        "{%0,%1,%2,%3}, {%4,%5,%6,%7}, {%8,%9}, {%0,%1,%2,%3};" \
        : "+f"((d)[0]), "+f"((d)[1]), "+f"((d)[2]), "+f"((d)[3]) \
        : "r"((a)[0]), "r"((a)[1]), "r"((a)[2]), "r"((a)[3]), "r"(b0_), "r"(b1_))

__device__ __forceinline__ uint32_t packh2(float s0, float s1){
    __half2 h2 = __floats2half2_rn(s0, s1);
    return *reinterpret_cast<uint32_t*>(&h2);
}
__device__ __forceinline__ uint32_t lrelu2(__half2 v, __half2 slope){
    __half2 o = __hmax2(v, __hmul2(v, slope));
    return *reinterpret_cast<uint32_t*>(&o);
}

// ---------------------------------------------------------------------------
// K1 fused: blocks [0,128) = GCN (512 thr, 4/node); blocks [128,164) = prep.
// (unchanged)
// ---------------------------------------------------------------------------
__global__ void __launch_bounds__(512)
k1_fused(const float* __restrict__ x,
         const float* __restrict__ Wg0, const float* __restrict__ bg0,
         const float* __restrict__ Wg1, const float* __restrict__ bg1,
         const float* __restrict__ Wg2, const float* __restrict__ bg2,
         const float* __restrict__ We1, const float* __restrict__ We2,
         float* __restrict__ h_out)
{
    const int tid = threadIdx.x;

    if (blockIdx.x >= 128){
        int idx = (blockIdx.x - 128)*512 + tid;
        if (idx < 128*128){
            int k = idx >> 7, n = idx & 127;
            g_Bhi[n*136 + k] = __float2half_rn(We1[k*128 + n]);
        } else if (idx < 128*128 + 128*16){
            int r = idx - 128*128;
            int k = r >> 4, c = r & 15;
            g_W2hi[c*136 + k] = __float2half_rn(We2[k*16 + c]);
        }
        return;
    }

    __shared__ float buf[128*33];
    __shared__ float Sp[16*33];
    __shared__ float SV[32];
    const int n  = tid >> 2;
    const int qf = tid & 3;
    const int base = blockIdx.x * NN;
    const float inv = 1.0f/127.0f;

    float xr[D_IN];
#pragma unroll
    for (int k=0;k<D_IN;k++) xr[k] = x[(base+n)*D_IN + k];
    if (qf == 0){
#pragma unroll
        for (int k=0;k<D_IN;k++) buf[n*33 + k] = xr[k];
    }
    __syncthreads();

    if (tid < 96){
        int col = tid % 6, grp = tid / 6;
        float s = 0.f;
#pragma unroll
        for (int m=0;m<8;m++) s += buf[(grp*8+m)*33 + col];
        Sp[grp*7 + col] = s;
    }
    __syncthreads();
    if (tid < 6){
        float s = 0.f;
#pragma unroll
        for (int g2=0;g2<16;g2++) s += Sp[g2*7 + tid];
        SV[tid] = s;
    }
    __syncthreads();

    float a0[8];
#pragma unroll
    for (int cc=0;cc<8;cc++){
        int c = qf*8 + cc;
        float y = 0.f, S = 0.f;
#pragma unroll
        for (int k=0;k<D_IN;k++){
            float w = __ldg(&Wg0[k*32+c]);
            y += xr[k]*w;  S += SV[k]*w;
        }
        a0[cc] = lrelu((S - y)*inv + __ldg(&bg0[c]));
    }
    __syncthreads();
#pragma unroll
    for (int cc=0;cc<8;cc++) buf[n*33 + qf*8 + cc] = a0[cc];
    __syncthreads();

    {
        int col = tid & 31, grp = tid >> 5;
        float s = 0.f;
#pragma unroll
        for (int m=0;m<8;m++) s += buf[(grp*8+m)*33 + col];
        Sp[grp*33 + col] = s;
    }
    __syncthreads();
    if (tid < 32){
        float s = 0.f;
#pragma unroll
        for (int g2=0;g2<16;g2++) s += Sp[g2*33 + tid];
        SV[tid] = s;
    }
    __syncthreads();

    float a1[8];
#pragma unroll
    for (int cc=0;cc<8;cc++){
        int c = qf*8 + cc;
        float y = 0.f, S = 0.f;
#pragma unroll
        for (int k=0;k<32;k++){
            float w = __ldg(&Wg1[k*32+c]);
            y += buf[n*33+k]*w;  S += SV[k]*w;
        }
        a1[cc] = lrelu((S - y)*inv + __ldg(&bg1[c]));
    }
    __syncthreads();
#pragma unroll
    for (int cc=0;cc<8;cc++) buf[n*33 + qf*8 + cc] = a1[cc];
    __syncthreads();

    {
        int col = tid & 31, grp = tid >> 5;
        float s = 0.f;
#pragma unroll
        for (int m=0;m<8;m++) s += buf[(grp*8+m)*33 + col];
        Sp[grp*33 + col] = s;
    }
    __syncthreads();
    if (tid < 32){
        float s = 0.f;
#pragma unroll
        for (int g2=0;g2<16;g2++) s += Sp[g2*33 + tid];
        SV[tid] = s;
    }
    __syncthreads();

#pragma unroll
    for (int cc=0;cc<16;cc++){
        int c = qf*16 + cc;
        float y = 0.f, S = 0.f;
#pragma unroll
        for (int k=0;k<32;k++){
            float w = __ldg(&Wg2[k*64+c]);
            y += buf[n*33+k]*w;  S += SV[k]*w;
        }
        h_out[(base+n)*64 + c] = (S - y)*inv + __ldg(&bg2[c]);
    }
}

// ---------------------------------------------------------------------------
// K2a: A0/B0 GEMM (fp16 out, be0 folded into B0). float4 hs loads. (unchanged)
// ---------------------------------------------------------------------------
__global__ void __launch_bounds__(256)
k2_ab(const float* __restrict__ h, const float* __restrict__ We0,
      const float* __restrict__ be0)
{
    __shared__ float hs[32*64];
    const int tid = threadIdx.x;
    const int n0 = blockIdx.x * 32;

    for (int l = tid; l < 32*64; l += 256) hs[l] = h[n0*64 + l];
    __syncthreads();

    const int col = tid & 127;
    const int kb  = (tid >> 7) * 64;
    const float bias = (tid >= 128) ? __ldg(&be0[col]) : 0.f;

    float acc[32];
#pragma unroll
    for (int i=0;i<32;i++) acc[i]=0.f;

    for (int k=0;k<64;k+=4){
        float w0 = __ldg(&We0[(kb+k+0)*128 + col]);
        float w1 = __ldg(&We0[(kb+k+1)*128 + col]);
        float w2 = __ldg(&We0[(kb+k+2)*128 + col]);
        float w3 = __ldg(&We0[(kb+k+3)*128 + col]);
#pragma unroll
        for (int nn=0;nn<32;nn++){
            float4 hv = *reinterpret_cast<const float4*>(&hs[nn*64 + k]);
            acc[nn] += hv.x*w0 + hv.y*w1 + hv.z*w2 + hv.w*w3;
        }
    }

    __half* dst = (tid < 128) ? g_A0h : g_B0h;
#pragma unroll
    for (int nn=0;nn<32;nn++)
        dst[(size_t)(n0+nn)*128 + col] = __float2half_rn(acc[nn] + bias);
}

// ---------------------------------------------------------------------------
// K2b: node MLP + diagonal 4x4 blocks of U. Side stream. (unchanged)
// ---------------------------------------------------------------------------
#define K2B_W0   0
#define K2B_W1   4096
#define K2B_W2   8192
#define K2B_BA   8960
#define K2B_BB   11136
#define K2B_VB   13312
#define K2B_B0   13728
#define K2B_B1   13792
#define K2B_B2   13856
#define K2B_SMEM ((13856+16)*4)

__global__ void __launch_bounds__(256)
k2b_node(const float* __restrict__ h,
         const float* __restrict__ Wn0, const float* __restrict__ bn0,
         const float* __restrict__ Wn1, const float* __restrict__ bn1,
         const float* __restrict__ Wn2, const float* __restrict__ bn2,
         float* __restrict__ U)
{
    extern __shared__ float sm[];
    const int tid = threadIdx.x;
    const int blk = blockIdx.x;
    const int ln  = tid >> 3;
    const int q   = tid & 7;
    const int b   = blk >> 2;
    const int n0  = (blk & 3) * 32;

    float4* w0s = reinterpret_cast<float4*>(sm + K2B_W0);
    float4* w1s = reinterpret_cast<float4*>(sm + K2B_W1);

    for (int l = tid; l < 1024; l += 256){
        w0s[l] = reinterpret_cast<const float4*>(Wn0)[l];
        w1s[l] = reinterpret_cast<const float4*>(Wn1)[l];
    }
    for (int l = tid; l < 768; l += 256){
        int k = l / 12, c = l % 12;
        sm[K2B_W2 + l] = (c < 10) ? Wn2[k*10 + c] : 0.f;
    }
    if (tid < 64){ sm[K2B_B0 + tid] = bn0[tid]; sm[K2B_B1 + tid] = bn1[tid]; }
    else if (tid < 76) sm[K2B_B2 + tid - 64] = (tid - 64 < 10) ? bn2[tid-64] : 0.f;
    for (int l = tid; l < 2048; l += 256){
        int r_ = l >> 6, c = l & 63;
        sm[K2B_BA + r_*68 + c] = h[(size_t)(b*128 + n0 + r_)*64 + c];
    }
    __syncthreads();

    {
        float acc[8];
#pragma unroll
        for (int m=0;m<8;m++) acc[m] = sm[K2B_B0 + q*8 + m];
        for (int k=0;k<64;k++){
            float hk = sm[K2B_BA + ln*68 + k];
            float4 wa = w0s[k*16 + q*2];
            float4 wb = w0s[k*16 + q*2 + 1];
            acc[0] += hk*wa.x; acc[1] += hk*wa.y; acc[2] += hk*wa.z; acc[3] += hk*wa.w;
            acc[4] += hk*wb.x; acc[5] += hk*wb.y; acc[6] += hk*wb.z; acc[7] += hk*wb.w;
        }
#pragma unroll
        for (int m=0;m<8;m++) sm[K2B_BB + ln*68 + q*8 + m] = lrelu(acc[m]);
    }
    __syncthreads();

    {
        float acc[8];
#pragma unroll
        for (int m=0;m<8;m++) acc[m] = sm[K2B_B1 + q*8 + m];
        for (int k=0;k<64;k++){
            float hk = sm[K2B_BB + ln*68 + k];
            float4 wa = w1s[k*16 + q*2];
            float4 wb = w1s[k*16 + q*2 + 1];
            acc[0] += hk*wa.x; acc[1] += hk*wa.y; acc[2] += hk*wa.z; acc[3] += hk*wa.w;
            acc[4] += hk*wb.x; acc[5] += hk*wb.y; acc[6] += hk*wb.z; acc[7] += hk*wb.w;
        }
        __syncthreads();
#pragma unroll
        for (int m=0;m<8;m++) sm[K2B_BA + ln*68 + q*8 + m] = lrelu(acc[m]);
    }
    __syncthreads();

    if (q < 6){
        const int c0 = 2*q, c1 = 2*q + 1;
        float a0 = sm[K2B_B2 + c0];
        float a1 = sm[K2B_B2 + c1];
        for (int k=0;k<64;k++){
            float hk = sm[K2B_BA + ln*68 + k];
            a0 += hk * sm[K2B_W2 + k*12 + c0];
            a1 += hk * sm[K2B_W2 + k*12 + c1];
        }
        sm[K2B_VB + ln*13 + c0] = a0;
        sm[K2B_VB + ln*13 + c1] = a1;
    }
    __syncthreads();

    if (q < 4){
        const int SMAT[16] = {0,1,2,3, 1,4,5,6, 2,5,7,8, 3,6,8,9};
        const int node = n0 + ln;
        float4 rv;
        rv.x = sm[K2B_VB + ln*13 + SMAT[q*4+0]];
        rv.y = sm[K2B_VB + ln*13 + SMAT[q*4+1]];
        rv.z = sm[K2B_VB + ln*13 + SMAT[q*4+2]];
        rv.w = sm[K2B_VB + ln*13 + SMAT[q*4+3]];
        float* Ub = U + (size_t)b*U_PER_B;
        *reinterpret_cast<float4*>(Ub + (size_t)(4*node+q)*U_STRIDE + 4*node) = rv;
    }
}

// ---------------------------------------------------------------------------
// K3: PERSISTENT edge MLP, warp tile = 16 rows x 128 cols.
// Per warp w: pair rows w*16..+15 (i = i0+w constant), full k-range owned ->
// GEMM2 chains in registers, direct scatter, no ES, only 2 barriers/tile.
// ---------------------------------------------------------------------------
#define OFF_BHI  0                    // 34816 (persistent)
#define OFF_W2HI 34816                // 4352  (persistent)
#define OFF_BE1  39168                // 512
#define OFF_BE2  39680                // 64
#define OFF_A0S  39744                // 8 x 272 B
#define OFF_B0S  41920                // 16 x 272 B
#define K3_SMEM  46272

#define K3_GRID  296
#define N_TILES  (72*BATCH)

__global__ void __launch_bounds__(256, 2)
k3_edge_mma(const float* __restrict__ be1,
            const float* __restrict__ be2,
            float* __restrict__ U)
{
    extern __shared__ char smem[];
    float* smemf = reinterpret_cast<float*>(smem);
    const uint32_t sb = smem_u32(smem);
    const int tid = threadIdx.x;
    const int w = tid >> 5;          // warp 0..7 -> pair rows w*16..+15
    const int lane = tid & 31;
    const int g = lane >> 2;
    const int r = lane & 3;

    // ---- stage persistent weights once ----
    {
        const uint4* sh  = reinterpret_cast<const uint4*>(g_Bhi);
        uint4* dh = reinterpret_cast<uint4*>(smem + OFF_BHI);
        for (int l = tid; l < 2176; l += 256) dh[l] = sh[l];
        const uint4* s2h = reinterpret_cast<const uint4*>(g_W2hi);
        uint4* d2h = reinterpret_cast<uint4*>(smem + OFF_W2HI);
        for (int l = tid; l < 272; l += 256) d2h[l] = s2h[l];
        if (tid < 128) smemf[OFF_BE1/4 + tid] = be1[tid];
        else if (tid < 144) smemf[OFF_BE2/4 + tid - 128] = be2[tid - 128];
    }

    // ldmatrix col-major B base (16-col footprint; no ng split)
    const uint32_t bOff = (uint32_t)(((((lane >> 4) << 3) + (lane & 7))*272)
                                    + ((lane >> 3) & 1)*16);
    const uint32_t bHi = sb + OFF_BHI + bOff;
    const uint32_t wHi = sb + OFF_W2HI + bOff;
    const __half2 slope = __floats2half2_rn(0.1f, 0.1f);

    const __half2* pA  = reinterpret_cast<const __half2*>(smem + OFF_A0S) + w*68;
    const __half2* pB0 = reinterpret_cast<const __half2*>(smem + OFF_B0S) + g*68;
    const __half2* pB1 = pB0 + 8*68;

    for (int tt = blockIdx.x; tt < N_TILES; tt += K3_GRID){
        const int tri = tt % 72;
        const int b   = tt / 72;
        int jt = 0;
#pragma unroll
        for (int q=1;q<8;q++) if (tri >= q*(q+1)) jt = q;
        const int it = tri - jt*(jt+1);
        const int i0 = it*8, j0 = jt*16;

        // ---- stage A0/B0 rows (fp16) ----
        if (tid < 128){
            int rr = tid >> 4, c16 = tid & 15;
            uint4 v = reinterpret_cast<const uint4*>(g_A0h + ((size_t)(b*NN + i0 + rr))*128)[c16];
            *reinterpret_cast<uint4*>(smem + OFF_A0S + rr*272 + c16*16) = v;
        } else {
            int l = tid - 128;
#pragma unroll
            for (int h2_ = 0; h2_ < 2; h2_++){
                int rr = (l + h2_*128) >> 4, c16 = (l + h2_*128) & 15;
                uint4 v = reinterpret_cast<const uint4*>(g_B0h + ((size_t)(b*NN + j0 + rr))*128)[c16];
                *reinterpret_cast<uint4*>(smem + OFF_B0S + rr*272 + c16*16) = v;
            }
        }
        __syncthreads();

        float acc[16][4];
#pragma unroll
        for (int a2=0;a2<16;a2++)
#pragma unroll
            for (int a3=0;a3<4;a3++) acc[a2][a3] = 0.f;

        // ---- GEMM1: A built once per warp (row group w), all 128 cols ----
#pragma unroll
        for (int ks = 0; ks < 8; ks++){
            __half2 aa  = pA[ks*8 + r];
            __half2 ab  = pA[ks*8 + 4 + r];
            __half2 b0a = pB0[ks*8 + r];
            __half2 b0b = pB0[ks*8 + 4 + r];
            __half2 b1a = pB1[ks*8 + r];
            __half2 b1b = pB1[ks*8 + 4 + r];

            uint32_t ah[4];
            ah[0] = lrelu2(__hadd2(aa, b0a), slope);
            ah[1] = lrelu2(__hadd2(aa, b1a), slope);
            ah[2] = lrelu2(__hadd2(ab, b0b), slope);
            ah[3] = lrelu2(__hadd2(ab, b1b), slope);

#pragma unroll
            for (int n2 = 0; n2 < 8; n2++){
                uint32_t bh[4];
                LDM4(bh, bHi + n2*4352 + ks*32);
                MMA16816H(acc[2*n2],   ah, bh[0], bh[1]);
                MMA16816H(acc[2*n2+1], ah, bh[2], bh[3]);
            }
        }

        // ---- GEMM2: full k-range per warp, chained in registers ----
        float e[2][4];
#pragma unroll
        for (int a2=0;a2<2;a2++)
#pragma unroll
            for (int a3=0;a3<4;a3++) e[a2][a3] = 0.f;

#pragma unroll
        for (int qk = 0; qk < 8; qk++){
            uint32_t bh[4];
            LDM4(bh, wHi + qk*32);
            const int cA = qk*16 + 2*r;
            const int cB = qk*16 + 8 + 2*r;
            float beA0 = smemf[OFF_BE1/4 + cA], beA1 = smemf[OFF_BE1/4 + cA + 1];
            float beB0 = smemf[OFF_BE1/4 + cB], beB1 = smemf[OFF_BE1/4 + cB + 1];
            uint32_t ah[4];
            ah[0] = packh2(lrelu(acc[2*qk][0]+beA0),   lrelu(acc[2*qk][1]+beA1));
            ah[1] = packh2(lrelu(acc[2*qk][2]+beA0),   lrelu(acc[2*qk][3]+beA1));
            ah[2] = packh2(lrelu(acc[2*qk+1][0]+beB0), lrelu(acc[2*qk+1][1]+beB1));
            ah[3] = packh2(lrelu(acc[2*qk+1][2]+beB0), lrelu(acc[2*qk+1][3]+beB1));
            MMA16816H(e[0], ah, bh[0], bh[1]);
            MMA16816H(e[1], ah, bh[2], bh[3]);
        }

        // ---- direct scatter into U ----
        {
            const int i = i0 + w;
            float* Ub = U + (size_t)b*U_PER_B;
#pragma unroll
            for (int rh = 0; rh < 2; rh++){
                const int j = j0 + g + rh*8;
                if (i < j){
#pragma unroll
                    for (int t_ = 0; t_ < 2; t_++){
                        const int c = t_*8 + 2*r;
                        float vx = e[t_][rh*2+0] + smemf[OFF_BE2/4 + c];
                        float vy = e[t_][rh*2+1] + smemf[OFF_BE2/4 + c + 1];
                        const int qq = c >> 2, m = c & 3;
                        float2 v2 = make_float2(vx, vy);
                        *reinterpret_cast<float2*>(Ub + (size_t)(4*i+qq)*U_STRIDE + 4*j + m) = v2;
                        *reinterpret_cast<float2*>(Ub + (size_t)(4*j+qq)*U_STRIDE + 4*i + m) = v2;
                    }
                }
            }
        }
        __syncthreads();   // protect A0S/B0S for next tile
    }
}

// ---------------------------------------------------------------------------
extern "C" void kernel_launch(void* const* d_in, const int* in_sizes, int n_in,
                              void* d_out, int out_size)
{
    const float* x   = (const float*)d_in[0];
    const float* Wg0 = (const float*)d_in[4];
    const float* bg0 = (const float*)d_in[5];
    const float* Wg1 = (const float*)d_in[6];
    const float* bg1 = (const float*)d_in[7];
    const float* Wg2 = (const float*)d_in[8];
    const float* bg2 = (const float*)d_in[9];
    const float* Wn0 = (const float*)d_in[10];
    const float* bn0 = (const float*)d_in[11];
    const float* Wn1 = (const float*)d_in[12];
    const float* bn1 = (const float*)d_in[13];
    const float* Wn2 = (const float*)d_in[14];
    const float* bn2 = (const float*)d_in[15];
    const float* We0 = (const float*)d_in[16];
    const float* be0 = (const float*)d_in[17];
    const float* We1 = (const float*)d_in[18];
    const float* be1 = (const float*)d_in[19];
    const float* We2 = (const float*)d_in[20];
    const float* be2 = (const float*)d_in[21];

    float* h_out = (float*)d_out;                 // (16384, 64)
    float* U     = h_out + (size_t)TOTAL*D_MP;    // (128, 512, 512)

    static bool init_done = false;
    static cudaStream_t s2;
    static cudaEvent_t ev_fork, ev_join;
    if (!init_done){
        cudaFuncSetAttribute(k3_edge_mma, cudaFuncAttributeMaxDynamicSharedMemorySize, K3_SMEM);
        cudaFuncSetAttribute(k2b_node, cudaFuncAttributeMaxDynamicSharedMemorySize, K2B_SMEM);
        cudaStreamCreateWithFlags(&s2, cudaStreamNonBlocking);
        cudaEventCreateWithFlags(&ev_fork, cudaEventDisableTiming);
        cudaEventCreateWithFlags(&ev_join, cudaEventDisableTiming);
        init_done = true;
    }

    // main stream: k1 -> k2_ab -> k3 ; side stream: k2b (forks after k1)
    k1_fused<<<164, 512>>>(x, Wg0,bg0, Wg1,bg1, Wg2,bg2, We1, We2, h_out);
    cudaEventRecord(ev_fork, 0);
    cudaStreamWaitEvent(s2, ev_fork, 0);
    k2b_node<<<512, 256, K2B_SMEM, s2>>>(h_out, Wn0,bn0, Wn1,bn1, Wn2,bn2, U);
    cudaEventRecord(ev_join, s2);
    k2_ab<<<512, 256>>>(h_out, We0, be0);
    k3_edge_mma<<<K3_GRID, 256, K3_SMEM>>>(be1, be2, U);
    cudaStreamWaitEvent(0, ev_join, 0);
}

// round 16
// speedup vs baseline: 1.0210x; 1.0210x over previous
#include <cuda_runtime.h>
#include <cuda_bf16.h>
#include <cuda_fp16.h>
#include <cstdint>

// Problem constants
#define BATCH 128
#define NN    128
#define D_IN  6
#define D_MP  64
#define TOTAL (BATCH*NN)    // 16384
#define U_STRIDE 512
#define U_PER_B  (512*512)

__device__ __half g_A0h[TOTAL*128];         // fp16(h @ We0[:64])
__device__ __half g_B0h[TOTAL*128];         // fp16(h @ We0[64:] + be0)
__device__ __half g_Bhi[128*136];           // We1^T fp16, padded [n][136]
__device__ __half g_W2hi[16*136];           // We2^T fp16, padded [c][136]

__device__ __forceinline__ float lrelu(float v){ return v >= 0.f ? v : 0.1f*v; }

__device__ __forceinline__ uint32_t smem_u32(const void* p){
    uint32_t a;
    asm("{ .reg .u64 t; cvta.to.shared.u64 t, %1; cvt.u32.u64 %0, t; }"
        : "=r"(a) : "l"(p));
    return a;
}

#define LDM4(r, addr) \
    asm volatile("ldmatrix.sync.aligned.m8n8.x4.shared.b16 {%0,%1,%2,%3}, [%4];" \
        : "=r"((r)[0]), "=r"((r)[1]), "=r"((r)[2]), "=r"((r)[3]) : "r"(addr))

#define MMA16816H(d, a, b0_, b1_) \
    asm volatile("mma.sync.aligned.m16n8k16.row.col.f32.f16.f16.f32 " \
        "{%0,%1,%2,%3}, {%4,%5,%6,%7}, {%8,%9}, {%0,%1,%2,%3};" \
        : "+f"((d)[0]), "+f"((d)[1]), "+f"((d)[2]), "+f"((d)[3]) \
        : "r"((a)[0]), "r"((a)[1]), "r"((a)[2]), "r"((a)[3]), "r"(b0_), "r"(b1_))

__device__ __forceinline__ uint32_t packh2(float s0, float s1){
    __half2 h2 = __floats2half2_rn(s0, s1);
    return *reinterpret_cast<uint32_t*>(&h2);
}
__device__ __forceinline__ uint32_t lrelu2(__half2 v, __half2 slope){
    __half2 o = __hmax2(v, __hmul2(v, slope));
    return *reinterpret_cast<uint32_t*>(&o);
}

__device__ __forceinline__ void cp16(uint32_t saddr, const void* gaddr){
    asm volatile("cp.async.cg.shared.global [%0], [%1], 16;"
        :: "r"(saddr), "l"(gaddr) : "memory");
}
#define CP_COMMIT() asm volatile("cp.async.commit_group;" ::: "memory")
#define CP_WAIT0()  asm volatile("cp.async.wait_group 0;" ::: "memory")

// ---------------------------------------------------------------------------
// K1 fused: blocks [0,128) = GCN (512 thr, 4/node); blocks [128,164) = prep.
// (unchanged)
// ---------------------------------------------------------------------------
__global__ void __launch_bounds__(512)
k1_fused(const float* __restrict__ x,
         const float* __restrict__ Wg0, const float* __restrict__ bg0,
         const float* __restrict__ Wg1, const float* __restrict__ bg1,
         const float* __restrict__ Wg2, const float* __restrict__ bg2,
         const float* __restrict__ We1, const float* __restrict__ We2,
         float* __restrict__ h_out)
{
    const int tid = threadIdx.x;

    if (blockIdx.x >= 128){
        int idx = (blockIdx.x - 128)*512 + tid;
        if (idx < 128*128){
            int k = idx >> 7, n = idx & 127;
            g_Bhi[n*136 + k] = __float2half_rn(We1[k*128 + n]);
        } else if (idx < 128*128 + 128*16){
            int r = idx - 128*128;
            int k = r >> 4, c = r & 15;
            g_W2hi[c*136 + k] = __float2half_rn(We2[k*16 + c]);
        }
        return;
    }

    __shared__ float buf[128*33];
    __shared__ float Sp[16*33];
    __shared__ float SV[32];
    const int n  = tid >> 2;
    const int qf = tid & 3;
    const int base = blockIdx.x * NN;
    const float inv = 1.0f/127.0f;

    float xr[D_IN];
#pragma unroll
    for (int k=0;k<D_IN;k++) xr[k] = x[(base+n)*D_IN + k];
    if (qf == 0){
#pragma unroll
        for (int k=0;k<D_IN;k++) buf[n*33 + k] = xr[k];
    }
    __syncthreads();

    if (tid < 96){
        int col = tid % 6, grp = tid / 6;
        float s = 0.f;
#pragma unroll
        for (int m=0;m<8;m++) s += buf[(grp*8+m)*33 + col];
        Sp[grp*7 + col] = s;
    }
    __syncthreads();
    if (tid < 6){
        float s = 0.f;
#pragma unroll
        for (int g2=0;g2<16;g2++) s += Sp[g2*7 + tid];
        SV[tid] = s;
    }
    __syncthreads();

    float a0[8];
#pragma unroll
    for (int cc=0;cc<8;cc++){
        int c = qf*8 + cc;
        float y = 0.f, S = 0.f;
#pragma unroll
        for (int k=0;k<D_IN;k++){
            float w = __ldg(&Wg0[k*32+c]);
            y += xr[k]*w;  S += SV[k]*w;
        }
        a0[cc] = lrelu((S - y)*inv + __ldg(&bg0[c]));
    }
    __syncthreads();
#pragma unroll
    for (int cc=0;cc<8;cc++) buf[n*33 + qf*8 + cc] = a0[cc];
    __syncthreads();

    {
        int col = tid & 31, grp = tid >> 5;
        float s = 0.f;
#pragma unroll
        for (int m=0;m<8;m++) s += buf[(grp*8+m)*33 + col];
        Sp[grp*33 + col] = s;
    }
    __syncthreads();
    if (tid < 32){
        float s = 0.f;
#pragma unroll
        for (int g2=0;g2<16;g2++) s += Sp[g2*33 + tid];
        SV[tid] = s;
    }
    __syncthreads();

    float a1[8];
#pragma unroll
    for (int cc=0;cc<8;cc++){
        int c = qf*8 + cc;
        float y = 0.f, S = 0.f;
#pragma unroll
        for (int k=0;k<32;k++){
            float w = __ldg(&Wg1[k*32+c]);
            y += buf[n*33+k]*w;  S += SV[k]*w;
        }
        a1[cc] = lrelu((S - y)*inv + __ldg(&bg1[c]));
    }
    __syncthreads();
#pragma unroll
    for (int cc=0;cc<8;cc++) buf[n*33 + qf*8 + cc] = a1[cc];
    __syncthreads();

    {
        int col = tid & 31, grp = tid >> 5;
        float s = 0.f;
#pragma unroll
        for (int m=0;m<8;m++) s += buf[(grp*8+m)*33 + col];
        Sp[grp*33 + col] = s;
    }
    __syncthreads();
    if (tid < 32){
        float s = 0.f;
#pragma unroll
        for (int g2=0;g2<16;g2++) s += Sp[g2*33 + tid];
        SV[tid] = s;
    }
    __syncthreads();

#pragma unroll
    for (int cc=0;cc<16;cc++){
        int c = qf*16 + cc;
        float y = 0.f, S = 0.f;
#pragma unroll
        for (int k=0;k<32;k++){
            float w = __ldg(&Wg2[k*64+c]);
            y += buf[n*33+k]*w;  S += SV[k]*w;
        }
        h_out[(base+n)*64 + c] = (S - y)*inv + __ldg(&bg2[c]);
    }
}

// ---------------------------------------------------------------------------
// K2a: A0/B0 GEMM (fp16 out, be0 folded into B0). float4 hs loads. (unchanged)
// ---------------------------------------------------------------------------
__global__ void __launch_bounds__(256)
k2_ab(const float* __restrict__ h, const float* __restrict__ We0,
      const float* __restrict__ be0)
{
    __shared__ float hs[32*64];
    const int tid = threadIdx.x;
    const int n0 = blockIdx.x * 32;

    for (int l = tid; l < 32*64; l += 256) hs[l] = h[n0*64 + l];
    __syncthreads();

    const int col = tid & 127;
    const int kb  = (tid >> 7) * 64;
    const float bias = (tid >= 128) ? __ldg(&be0[col]) : 0.f;

    float acc[32];
#pragma unroll
    for (int i=0;i<32;i++) acc[i]=0.f;

    for (int k=0;k<64;k+=4){
        float w0 = __ldg(&We0[(kb+k+0)*128 + col]);
        float w1 = __ldg(&We0[(kb+k+1)*128 + col]);
        float w2 = __ldg(&We0[(kb+k+2)*128 + col]);
        float w3 = __ldg(&We0[(kb+k+3)*128 + col]);
#pragma unroll
        for (int nn=0;nn<32;nn++){
            float4 hv = *reinterpret_cast<const float4*>(&hs[nn*64 + k]);
            acc[nn] += hv.x*w0 + hv.y*w1 + hv.z*w2 + hv.w*w3;
        }
    }

    __half* dst = (tid < 128) ? g_A0h : g_B0h;
#pragma unroll
    for (int nn=0;nn<32;nn++)
        dst[(size_t)(n0+nn)*128 + col] = __float2half_rn(acc[nn] + bias);
}

// ---------------------------------------------------------------------------
// K2b: node MLP + diagonal 4x4 blocks of U. Side stream. (unchanged)
// ---------------------------------------------------------------------------
#define K2B_W0   0
#define K2B_W1   4096
#define K2B_W2   8192
#define K2B_BA   8960
#define K2B_BB   11136
#define K2B_VB   13312
#define K2B_B0   13728
#define K2B_B1   13792
#define K2B_B2   13856
#define K2B_SMEM ((13856+16)*4)

__global__ void __launch_bounds__(256)
k2b_node(const float* __restrict__ h,
         const float* __restrict__ Wn0, const float* __restrict__ bn0,
         const float* __restrict__ Wn1, const float* __restrict__ bn1,
         const float* __restrict__ Wn2, const float* __restrict__ bn2,
         float* __restrict__ U)
{
    extern __shared__ float sm[];
    const int tid = threadIdx.x;
    const int blk = blockIdx.x;
    const int ln  = tid >> 3;
    const int q   = tid & 7;
    const int b   = blk >> 2;
    const int n0  = (blk & 3) * 32;

    float4* w0s = reinterpret_cast<float4*>(sm + K2B_W0);
    float4* w1s = reinterpret_cast<float4*>(sm + K2B_W1);

    for (int l = tid; l < 1024; l += 256){
        w0s[l] = reinterpret_cast<const float4*>(Wn0)[l];
        w1s[l] = reinterpret_cast<const float4*>(Wn1)[l];
    }
    for (int l = tid; l < 768; l += 256){
        int k = l / 12, c = l % 12;
        sm[K2B_W2 + l] = (c < 10) ? Wn2[k*10 + c] : 0.f;
    }
    if (tid < 64){ sm[K2B_B0 + tid] = bn0[tid]; sm[K2B_B1 + tid] = bn1[tid]; }
    else if (tid < 76) sm[K2B_B2 + tid - 64] = (tid - 64 < 10) ? bn2[tid-64] : 0.f;
    for (int l = tid; l < 2048; l += 256){
        int r_ = l >> 6, c = l & 63;
        sm[K2B_BA + r_*68 + c] = h[(size_t)(b*128 + n0 + r_)*64 + c];
    }
    __syncthreads();

    {
        float acc[8];
#pragma unroll
        for (int m=0;m<8;m++) acc[m] = sm[K2B_B0 + q*8 + m];
        for (int k=0;k<64;k++){
            float hk = sm[K2B_BA + ln*68 + k];
            float4 wa = w0s[k*16 + q*2];
            float4 wb = w0s[k*16 + q*2 + 1];
            acc[0] += hk*wa.x; acc[1] += hk*wa.y; acc[2] += hk*wa.z; acc[3] += hk*wa.w;
            acc[4] += hk*wb.x; acc[5] += hk*wb.y; acc[6] += hk*wb.z; acc[7] += hk*wb.w;
        }
#pragma unroll
        for (int m=0;m<8;m++) sm[K2B_BB + ln*68 + q*8 + m] = lrelu(acc[m]);
    }
    __syncthreads();

    {
        float acc[8];
#pragma unroll
        for (int m=0;m<8;m++) acc[m] = sm[K2B_B1 + q*8 + m];
        for (int k=0;k<64;k++){
            float hk = sm[K2B_BB + ln*68 + k];
            float4 wa = w1s[k*16 + q*2];
            float4 wb = w1s[k*16 + q*2 + 1];
            acc[0] += hk*wa.x; acc[1] += hk*wa.y; acc[2] += hk*wa.z; acc[3] += hk*wa.w;
            acc[4] += hk*wb.x; acc[5] += hk*wb.y; acc[6] += hk*wb.z; acc[7] += hk*wb.w;
        }
        __syncthreads();
#pragma unroll
        for (int m=0;m<8;m++) sm[K2B_BA + ln*68 + q*8 + m] = lrelu(acc[m]);
    }
    __syncthreads();

    if (q < 6){
        const int c0 = 2*q, c1 = 2*q + 1;
        float a0 = sm[K2B_B2 + c0];
        float a1 = sm[K2B_B2 + c1];
        for (int k=0;k<64;k++){
            float hk = sm[K2B_BA + ln*68 + k];
            a0 += hk * sm[K2B_W2 + k*12 + c0];
            a1 += hk * sm[K2B_W2 + k*12 + c1];
        }
        sm[K2B_VB + ln*13 + c0] = a0;
        sm[K2B_VB + ln*13 + c1] = a1;
    }
    __syncthreads();

    if (q < 4){
        const int SMAT[16] = {0,1,2,3, 1,4,5,6, 2,5,7,8, 3,6,8,9};
        const int node = n0 + ln;
        float4 rv;
        rv.x = sm[K2B_VB + ln*13 + SMAT[q*4+0]];
        rv.y = sm[K2B_VB + ln*13 + SMAT[q*4+1]];
        rv.z = sm[K2B_VB + ln*13 + SMAT[q*4+2]];
        rv.w = sm[K2B_VB + ln*13 + SMAT[q*4+3]];
        float* Ub = U + (size_t)b*U_PER_B;
        *reinterpret_cast<float4*>(Ub + (size_t)(4*node+q)*U_STRIDE + 4*node) = rv;
    }
}

// ---------------------------------------------------------------------------
// K3: PERSISTENT edge MLP, warp tile = 16 rows x 128 cols, DOUBLE-BUFFERED
// cp.async staging of A0/B0 (next tile loads overlap current compute).
// ---------------------------------------------------------------------------
#define OFF_BHI  0                    // 34816 (persistent)
#define OFF_W2HI 34816                // 4352  (persistent)
#define OFF_BE1  39168                // 512
#define OFF_BE2  39680                // 64
#define OFF_S0   39744                // stage buf 0: A(8x272) + B(16x272) = 6528
#define OFF_S1   46272                // stage buf 1
#define K3_SMEM  52800

#define K3_GRID  296
#define N_TILES  (72*BATCH)

__device__ __forceinline__ void k3_tdec(int tt, int& b, int& i0, int& j0){
    int tri = tt % 72; b = tt / 72;
    int jt = 0;
#pragma unroll
    for (int q=1;q<8;q++) if (tri >= q*(q+1)) jt = q;
    int it = tri - jt*(jt+1);
    i0 = it*8; j0 = jt*16;
}

__device__ __forceinline__ void k3_stage(uint32_t sbase, int b, int i0, int j0, int tid){
    if (tid < 128){
        int rr = tid >> 4, c16 = tid & 15;
        cp16(sbase + rr*272 + c16*16,
             g_A0h + ((size_t)(b*NN + i0 + rr))*128 + c16*8);
    } else {
        int l = tid - 128;
#pragma unroll
        for (int h2_ = 0; h2_ < 2; h2_++){
            int idx = l + h2_*128;
            int rr = idx >> 4, c16 = idx & 15;
            cp16(sbase + 2176 + rr*272 + c16*16,
                 g_B0h + ((size_t)(b*NN + j0 + rr))*128 + c16*8);
        }
    }
}

__global__ void __launch_bounds__(256, 2)
k3_edge_mma(const float* __restrict__ be1,
            const float* __restrict__ be2,
            float* __restrict__ U)
{
    extern __shared__ char smem[];
    float* smemf = reinterpret_cast<float*>(smem);
    const uint32_t sb = smem_u32(smem);
    const int tid = threadIdx.x;
    const int w = tid >> 5;          // warp 0..7 -> pair rows w*16..+15
    const int lane = tid & 31;
    const int g = lane >> 2;
    const int r = lane & 3;

    // ---- stage persistent weights once ----
    {
        const uint4* sh  = reinterpret_cast<const uint4*>(g_Bhi);
        uint4* dh = reinterpret_cast<uint4*>(smem + OFF_BHI);
        for (int l = tid; l < 2176; l += 256) dh[l] = sh[l];
        const uint4* s2h = reinterpret_cast<const uint4*>(g_W2hi);
        uint4* d2h = reinterpret_cast<uint4*>(smem + OFF_W2HI);
        for (int l = tid; l < 272; l += 256) d2h[l] = s2h[l];
        if (tid < 128) smemf[OFF_BE1/4 + tid] = be1[tid];
        else if (tid < 144) smemf[OFF_BE2/4 + tid - 128] = be2[tid - 128];
    }

    const uint32_t bOff = (uint32_t)(((((lane >> 4) << 3) + (lane & 7))*272)
                                    + ((lane >> 3) & 1)*16);
    const uint32_t bHi = sb + OFF_BHI + bOff;
    const uint32_t wHi = sb + OFF_W2HI + bOff;
    const __half2 slope = __floats2half2_rn(0.1f, 0.1f);

    // ---- prologue: stage first tile into buf0 ----
    int tt = blockIdx.x;
    if (tt < N_TILES){
        int b0_, pi0, pj0;
        k3_tdec(tt, b0_, pi0, pj0);
        k3_stage(sb + OFF_S0, b0_, pi0, pj0, tid);
    }
    CP_COMMIT();

    int cur = 0;
    for (; tt < N_TILES; tt += K3_GRID){
        int b, i0, j0;
        k3_tdec(tt, b, i0, j0);

        CP_WAIT0();
        __syncthreads();

        // issue next tile's loads into the other buffer
        const int nt = tt + K3_GRID;
        if (nt < N_TILES){
            int nb, ni0, nj0;
            k3_tdec(nt, nb, ni0, nj0);
            k3_stage(sb + (cur ? OFF_S0 : OFF_S1), nb, ni0, nj0, tid);
        }
        CP_COMMIT();

        const uint32_t sA = cur ? OFF_S1 : OFF_S0;
        const __half2* pA  = reinterpret_cast<const __half2*>(smem + sA) + w*68;
        const __half2* pB0 = reinterpret_cast<const __half2*>(smem + sA + 2176) + g*68;
        const __half2* pB1 = pB0 + 8*68;

        float acc[16][4];
#pragma unroll
        for (int a2=0;a2<16;a2++)
#pragma unroll
            for (int a3=0;a3<4;a3++) acc[a2][a3] = 0.f;

        // ---- GEMM1: A built once per warp (row group w), all 128 cols ----
#pragma unroll
        for (int ks = 0; ks < 8; ks++){
            __half2 aa  = pA[ks*8 + r];
            __half2 ab  = pA[ks*8 + 4 + r];
            __half2 b0a = pB0[ks*8 + r];
            __half2 b0b = pB0[ks*8 + 4 + r];
            __half2 b1a = pB1[ks*8 + r];
            __half2 b1b = pB1[ks*8 + 4 + r];

            uint32_t ah[4];
            ah[0] = lrelu2(__hadd2(aa, b0a), slope);
            ah[1] = lrelu2(__hadd2(aa, b1a), slope);
            ah[2] = lrelu2(__hadd2(ab, b0b), slope);
            ah[3] = lrelu2(__hadd2(ab, b1b), slope);

#pragma unroll
            for (int n2 = 0; n2 < 8; n2++){
                uint32_t bh[4];
                LDM4(bh, bHi + n2*4352 + ks*32);
                MMA16816H(acc[2*n2],   ah, bh[0], bh[1]);
                MMA16816H(acc[2*n2+1], ah, bh[2], bh[3]);
            }
        }

        // ---- GEMM2: full k-range per warp, chained in registers ----
        float e[2][4];
#pragma unroll
        for (int a2=0;a2<2;a2++)
#pragma unroll
            for (int a3=0;a3<4;a3++) e[a2][a3] = 0.f;

#pragma unroll
        for (int qk = 0; qk < 8; qk++){
            uint32_t bh[4];
            LDM4(bh, wHi + qk*32);
            const int cA = qk*16 + 2*r;
            const int cB = qk*16 + 8 + 2*r;
            float beA0 = smemf[OFF_BE1/4 + cA], beA1 = smemf[OFF_BE1/4 + cA + 1];
            float beB0 = smemf[OFF_BE1/4 + cB], beB1 = smemf[OFF_BE1/4 + cB + 1];
            uint32_t ah[4];
            ah[0] = packh2(lrelu(acc[2*qk][0]+beA0),   lrelu(acc[2*qk][1]+beA1));
            ah[1] = packh2(lrelu(acc[2*qk][2]+beA0),   lrelu(acc[2*qk][3]+beA1));
            ah[2] = packh2(lrelu(acc[2*qk+1][0]+beB0), lrelu(acc[2*qk+1][1]+beB1));
            ah[3] = packh2(lrelu(acc[2*qk+1][2]+beB0), lrelu(acc[2*qk+1][3]+beB1));
            MMA16816H(e[0], ah, bh[0], bh[1]);
            MMA16816H(e[1], ah, bh[2], bh[3]);
        }

        // ---- direct scatter into U ----
        {
            const int i = i0 + w;
            float* Ub = U + (size_t)b*U_PER_B;
#pragma unroll
            for (int rh = 0; rh < 2; rh++){
                const int j = j0 + g + rh*8;
                if (i < j){
#pragma unroll
                    for (int t_ = 0; t_ < 2; t_++){
                        const int c = t_*8 + 2*r;
                        float vx = e[t_][rh*2+0] + smemf[OFF_BE2/4 + c];
                        float vy = e[t_][rh*2+1] + smemf[OFF_BE2/4 + c + 1];
                        const int qq = c >> 2, m = c & 3;
                        float2 v2 = make_float2(vx, vy);
                        *reinterpret_cast<float2*>(Ub + (size_t)(4*i+qq)*U_STRIDE + 4*j + m) = v2;
                        *reinterpret_cast<float2*>(Ub + (size_t)(4*j+qq)*U_STRIDE + 4*i + m) = v2;
                    }
                }
            }
        }
        cur ^= 1;
    }
}

// ---------------------------------------------------------------------------
extern "C" void kernel_launch(void* const* d_in, const int* in_sizes, int n_in,
                              void* d_out, int out_size)
{
    const float* x   = (const float*)d_in[0];
    const float* Wg0 = (const float*)d_in[4];
    const float* bg0 = (const float*)d_in[5];
    const float* Wg1 = (const float*)d_in[6];
    const float* bg1 = (const float*)d_in[7];
    const float* Wg2 = (const float*)d_in[8];
    const float* bg2 = (const float*)d_in[9];
    const float* Wn0 = (const float*)d_in[10];
    const float* bn0 = (const float*)d_in[11];
    const float* Wn1 = (const float*)d_in[12];
    const float* bn1 = (const float*)d_in[13];
    const float* Wn2 = (const float*)d_in[14];
    const float* bn2 = (const float*)d_in[15];
    const float* We0 = (const float*)d_in[16];
    const float* be0 = (const float*)d_in[17];
    const float* We1 = (const float*)d_in[18];
    const float* be1 = (const float*)d_in[19];
    const float* We2 = (const float*)d_in[20];
    const float* be2 = (const float*)d_in[21];

    float* h_out = (float*)d_out;                 // (16384, 64)
    float* U     = h_out + (size_t)TOTAL*D_MP;    // (128, 512, 512)

    static bool init_done = false;
    static cudaStream_t s2;
    static cudaEvent_t ev_fork, ev_join;
    if (!init_done){
        cudaFuncSetAttribute(k3_edge_mma, cudaFuncAttributeMaxDynamicSharedMemorySize, K3_SMEM);
        cudaFuncSetAttribute(k2b_node, cudaFuncAttributeMaxDynamicSharedMemorySize, K2B_SMEM);
        cudaStreamCreateWithFlags(&s2, cudaStreamNonBlocking);
        cudaEventCreateWithFlags(&ev_fork, cudaEventDisableTiming);
        cudaEventCreateWithFlags(&ev_join, cudaEventDisableTiming);
        init_done = true;
    }

    // main stream: k1 -> k2_ab -> k3 ; side stream: k2b (forks after k1)
    k1_fused<<<164, 512>>>(x, Wg0,bg0, Wg1,bg1, Wg2,bg2, We1, We2, h_out);
    cudaEventRecord(ev_fork, 0);
    cudaStreamWaitEvent(s2, ev_fork, 0);
    k2b_node<<<512, 256, K2B_SMEM, s2>>>(h_out, Wn0,bn0, Wn1,bn1, Wn2,bn2, U);
    cudaEventRecord(ev_join, s2);
    k2_ab<<<512, 256>>>(h_out, We0, be0);
    k3_edge_mma<<<K3_GRID, 256, K3_SMEM>>>(be1, be2, U);
    cudaStreamWaitEvent(0, ev_join, 0);
}

// round 17
// speedup vs baseline: 1.0277x; 1.0066x over previous
#include <cuda_runtime.h>
#include <cuda_bf16.h>
#include <cuda_fp16.h>
#include <cstdint>

// Problem constants
#define BATCH 128
#define NN    128
#define D_IN  6
#define D_MP  64
#define TOTAL (BATCH*NN)    // 16384
#define U_STRIDE 512
#define U_PER_B  (512*512)

__device__ __half g_A0h[TOTAL*128];         // fp16(h @ We0[:64])
__device__ __half g_B0h[TOTAL*128];         // fp16(h @ We0[64:] + be0)
__device__ __half g_Bhi[128*136];           // We1^T fp16, padded [n][136]
__device__ __half g_W2hi[16*136];           // We2^T fp16, padded [c][136]

__device__ __forceinline__ float lrelu(float v){ return v >= 0.f ? v : 0.1f*v; }

__device__ __forceinline__ uint32_t smem_u32(const void* p){
    uint32_t a;
    asm("{ .reg .u64 t; cvta.to.shared.u64 t, %1; cvt.u32.u64 %0, t; }"
        : "=r"(a) : "l"(p));
    return a;
}

#define LDM4(r, addr) \
    asm volatile("ldmatrix.sync.aligned.m8n8.x4.shared.b16 {%0,%1,%2,%3}, [%4];" \
        : "=r"((r)[0]), "=r"((r)[1]), "=r"((r)[2]), "=r"((r)[3]) : "r"(addr))

#define MMA16816H(d, a, b0_, b1_) \
    asm volatile("mma.sync.aligned.m16n8k16.row.col.f32.f16.f16.f32 " \
        "{%0,%1,%2,%3}, {%4,%5,%6,%7}, {%8,%9}, {%0,%1,%2,%3};" \
        : "+f"((d)[0]), "+f"((d)[1]), "+f"((d)[2]), "+f"((d)[3]) \
        : "r"((a)[0]), "r"((a)[1]), "r"((a)[2]), "r"((a)[3]), "r"(b0_), "r"(b1_))

__device__ __forceinline__ uint32_t packh2(float s0, float s1){
    __half2 h2 = __floats2half2_rn(s0, s1);
    return *reinterpret_cast<uint32_t*>(&h2);
}
__device__ __forceinline__ uint32_t lrelu2(__half2 v, __half2 slope){
    __half2 o = __hmax2(v, __hmul2(v, slope));
    return *reinterpret_cast<uint32_t*>(&o);
}

__device__ __forceinline__ void cp16(uint32_t saddr, const void* gaddr){
    asm volatile("cp.async.cg.shared.global [%0], [%1], 16;"
        :: "r"(saddr), "l"(gaddr) : "memory");
}
#define CP_COMMIT() asm volatile("cp.async.commit_group;" ::: "memory")
#define CP_WAIT0()  asm volatile("cp.async.wait_group 0;" ::: "memory")

// ---------------------------------------------------------------------------
// K1 fused: blocks [0,128) = GCN (512 thr, 4/node); blocks [128,164) = prep.
// (unchanged)
// ---------------------------------------------------------------------------
__global__ void __launch_bounds__(512)
k1_fused(const float* __restrict__ x,
         const float* __restrict__ Wg0, const float* __restrict__ bg0,
         const float* __restrict__ Wg1, const float* __restrict__ bg1,
         const float* __restrict__ Wg2, const float* __restrict__ bg2,
         const float* __restrict__ We1, const float* __restrict__ We2,
         float* __restrict__ h_out)
{
    const int tid = threadIdx.x;

    if (blockIdx.x >= 128){
        int idx = (blockIdx.x - 128)*512 + tid;
        if (idx < 128*128){
            int k = idx >> 7, n = idx & 127;
            g_Bhi[n*136 + k] = __float2half_rn(We1[k*128 + n]);
        } else if (idx < 128*128 + 128*16){
            int r = idx - 128*128;
            int k = r >> 4, c = r & 15;
            g_W2hi[c*136 + k] = __float2half_rn(We2[k*16 + c]);
        }
        return;
    }

    __shared__ float buf[128*33];
    __shared__ float Sp[16*33];
    __shared__ float SV[32];
    const int n  = tid >> 2;
    const int qf = tid & 3;
    const int base = blockIdx.x * NN;
    const float inv = 1.0f/127.0f;

    float xr[D_IN];
#pragma unroll
    for (int k=0;k<D_IN;k++) xr[k] = x[(base+n)*D_IN + k];
    if (qf == 0){
#pragma unroll
        for (int k=0;k<D_IN;k++) buf[n*33 + k] = xr[k];
    }
    __syncthreads();

    if (tid < 96){
        int col = tid % 6, grp = tid / 6;
        float s = 0.f;
#pragma unroll
        for (int m=0;m<8;m++) s += buf[(grp*8+m)*33 + col];
        Sp[grp*7 + col] = s;
    }
    __syncthreads();
    if (tid < 6){
        float s = 0.f;
#pragma unroll
        for (int g2=0;g2<16;g2++) s += Sp[g2*7 + tid];
        SV[tid] = s;
    }
    __syncthreads();

    float a0[8];
#pragma unroll
    for (int cc=0;cc<8;cc++){
        int c = qf*8 + cc;
        float y = 0.f, S = 0.f;
#pragma unroll
        for (int k=0;k<D_IN;k++){
            float w = __ldg(&Wg0[k*32+c]);
            y += xr[k]*w;  S += SV[k]*w;
        }
        a0[cc] = lrelu((S - y)*inv + __ldg(&bg0[c]));
    }
    __syncthreads();
#pragma unroll
    for (int cc=0;cc<8;cc++) buf[n*33 + qf*8 + cc] = a0[cc];
    __syncthreads();

    {
        int col = tid & 31, grp = tid >> 5;
        float s = 0.f;
#pragma unroll
        for (int m=0;m<8;m++) s += buf[(grp*8+m)*33 + col];
        Sp[grp*33 + col] = s;
    }
    __syncthreads();
    if (tid < 32){
        float s = 0.f;
#pragma unroll
        for (int g2=0;g2<16;g2++) s += Sp[g2*33 + tid];
        SV[tid] = s;
    }
    __syncthreads();

    float a1[8];
#pragma unroll
    for (int cc=0;cc<8;cc++){
        int c = qf*8 + cc;
        float y = 0.f, S = 0.f;
#pragma unroll
        for (int k=0;k<32;k++){
            float w = __ldg(&Wg1[k*32+c]);
            y += buf[n*33+k]*w;  S += SV[k]*w;
        }
        a1[cc] = lrelu((S - y)*inv + __ldg(&bg1[c]));
    }
    __syncthreads();
#pragma unroll
    for (int cc=0;cc<8;cc++) buf[n*33 + qf*8 + cc] = a1[cc];
    __syncthreads();

    {
        int col = tid & 31, grp = tid >> 5;
        float s = 0.f;
#pragma unroll
        for (int m=0;m<8;m++) s += buf[(grp*8+m)*33 + col];
        Sp[grp*33 + col] = s;
    }
    __syncthreads();
    if (tid < 32){
        float s = 0.f;
#pragma unroll
        for (int g2=0;g2<16;g2++) s += Sp[g2*33 + tid];
        SV[tid] = s;
    }
    __syncthreads();

#pragma unroll
    for (int cc=0;cc<16;cc++){
        int c = qf*16 + cc;
        float y = 0.f, S = 0.f;
#pragma unroll
        for (int k=0;k<32;k++){
            float w = __ldg(&Wg2[k*64+c]);
            y += buf[n*33+k]*w;  S += SV[k]*w;
        }
        h_out[(base+n)*64 + c] = (S - y)*inv + __ldg(&bg2[c]);
    }
}

// ---------------------------------------------------------------------------
// K2a: A0/B0 GEMM (fp16 out, be0 folded into B0). float4 hs loads. (unchanged)
// ---------------------------------------------------------------------------
__global__ void __launch_bounds__(256)
k2_ab(const float* __restrict__ h, const float* __restrict__ We0,
      const float* __restrict__ be0)
{
    __shared__ float hs[32*64];
    const int tid = threadIdx.x;
    const int n0 = blockIdx.x * 32;

    for (int l = tid; l < 32*64; l += 256) hs[l] = h[n0*64 + l];
    __syncthreads();

    const int col = tid & 127;
    const int kb  = (tid >> 7) * 64;
    const float bias = (tid >= 128) ? __ldg(&be0[col]) : 0.f;

    float acc[32];
#pragma unroll
    for (int i=0;i<32;i++) acc[i]=0.f;

    for (int k=0;k<64;k+=4){
        float w0 = __ldg(&We0[(kb+k+0)*128 + col]);
        float w1 = __ldg(&We0[(kb+k+1)*128 + col]);
        float w2 = __ldg(&We0[(kb+k+2)*128 + col]);
        float w3 = __ldg(&We0[(kb+k+3)*128 + col]);
#pragma unroll
        for (int nn=0;nn<32;nn++){
            float4 hv = *reinterpret_cast<const float4*>(&hs[nn*64 + k]);
            acc[nn] += hv.x*w0 + hv.y*w1 + hv.z*w2 + hv.w*w3;
        }
    }

    __half* dst = (tid < 128) ? g_A0h : g_B0h;
#pragma unroll
    for (int nn=0;nn<32;nn++)
        dst[(size_t)(n0+nn)*128 + col] = __float2half_rn(acc[nn] + bias);
}

// ---------------------------------------------------------------------------
// K2b: node MLP + diagonal 4x4 blocks of U. Side stream. (unchanged)
// ---------------------------------------------------------------------------
#define K2B_W0   0
#define K2B_W1   4096
#define K2B_W2   8192
#define K2B_BA   8960
#define K2B_BB   11136
#define K2B_VB   13312
#define K2B_B0   13728
#define K2B_B1   13792
#define K2B_B2   13856
#define K2B_SMEM ((13856+16)*4)

__global__ void __launch_bounds__(256)
k2b_node(const float* __restrict__ h,
         const float* __restrict__ Wn0, const float* __restrict__ bn0,
         const float* __restrict__ Wn1, const float* __restrict__ bn1,
         const float* __restrict__ Wn2, const float* __restrict__ bn2,
         float* __restrict__ U)
{
    extern __shared__ float sm[];
    const int tid = threadIdx.x;
    const int blk = blockIdx.x;
    const int ln  = tid >> 3;
    const int q   = tid & 7;
    const int b   = blk >> 2;
    const int n0  = (blk & 3) * 32;

    float4* w0s = reinterpret_cast<float4*>(sm + K2B_W0);
    float4* w1s = reinterpret_cast<float4*>(sm + K2B_W1);

    for (int l = tid; l < 1024; l += 256){
        w0s[l] = reinterpret_cast<const float4*>(Wn0)[l];
        w1s[l] = reinterpret_cast<const float4*>(Wn1)[l];
    }
    for (int l = tid; l < 768; l += 256){
        int k = l / 12, c = l % 12;
        sm[K2B_W2 + l] = (c < 10) ? Wn2[k*10 + c] : 0.f;
    }
    if (tid < 64){ sm[K2B_B0 + tid] = bn0[tid]; sm[K2B_B1 + tid] = bn1[tid]; }
    else if (tid < 76) sm[K2B_B2 + tid - 64] = (tid - 64 < 10) ? bn2[tid-64] : 0.f;
    for (int l = tid; l < 2048; l += 256){
        int r_ = l >> 6, c = l & 63;
        sm[K2B_BA + r_*68 + c] = h[(size_t)(b*128 + n0 + r_)*64 + c];
    }
    __syncthreads();

    {
        float acc[8];
#pragma unroll
        for (int m=0;m<8;m++) acc[m] = sm[K2B_B0 + q*8 + m];
        for (int k=0;k<64;k++){
            float hk = sm[K2B_BA + ln*68 + k];
            float4 wa = w0s[k*16 + q*2];
            float4 wb = w0s[k*16 + q*2 + 1];
            acc[0] += hk*wa.x; acc[1] += hk*wa.y; acc[2] += hk*wa.z; acc[3] += hk*wa.w;
            acc[4] += hk*wb.x; acc[5] += hk*wb.y; acc[6] += hk*wb.z; acc[7] += hk*wb.w;
        }
#pragma unroll
        for (int m=0;m<8;m++) sm[K2B_BB + ln*68 + q*8 + m] = lrelu(acc[m]);
    }
    __syncthreads();

    {
        float acc[8];
#pragma unroll
        for (int m=0;m<8;m++) acc[m] = sm[K2B_B1 + q*8 + m];
        for (int k=0;k<64;k++){
            float hk = sm[K2B_BB + ln*68 + k];
            float4 wa = w1s[k*16 + q*2];
            float4 wb = w1s[k*16 + q*2 + 1];
            acc[0] += hk*wa.x; acc[1] += hk*wa.y; acc[2] += hk*wa.z; acc[3] += hk*wa.w;
            acc[4] += hk*wb.x; acc[5] += hk*wb.y; acc[6] += hk*wb.z; acc[7] += hk*wb.w;
        }
        __syncthreads();
#pragma unroll
        for (int m=0;m<8;m++) sm[K2B_BA + ln*68 + q*8 + m] = lrelu(acc[m]);
    }
    __syncthreads();

    if (q < 6){
        const int c0 = 2*q, c1 = 2*q + 1;
        float a0 = sm[K2B_B2 + c0];
        float a1 = sm[K2B_B2 + c1];
        for (int k=0;k<64;k++){
            float hk = sm[K2B_BA + ln*68 + k];
            a0 += hk * sm[K2B_W2 + k*12 + c0];
            a1 += hk * sm[K2B_W2 + k*12 + c1];
        }
        sm[K2B_VB + ln*13 + c0] = a0;
        sm[K2B_VB + ln*13 + c1] = a1;
    }
    __syncthreads();

    if (q < 4){
        const int SMAT[16] = {0,1,2,3, 1,4,5,6, 2,5,7,8, 3,6,8,9};
        const int node = n0 + ln;
        float4 rv;
        rv.x = sm[K2B_VB + ln*13 + SMAT[q*4+0]];
        rv.y = sm[K2B_VB + ln*13 + SMAT[q*4+1]];
        rv.z = sm[K2B_VB + ln*13 + SMAT[q*4+2]];
        rv.w = sm[K2B_VB + ln*13 + SMAT[q*4+3]];
        float* Ub = U + (size_t)b*U_PER_B;
        *reinterpret_cast<float4*>(Ub + (size_t)(4*node+q)*U_STRIDE + 4*node) = rv;
    }
}

// ---------------------------------------------------------------------------
// K3: PERSISTENT edge MLP, warp tile = 16 rows x 128 cols computed in TWO
// column passes (64 cols each) -> half the accumulators -> 3 CTAs/SM.
// Double-buffered cp.async staging of A0/B0.
// ---------------------------------------------------------------------------
#define OFF_BHI  0                    // 34816 (persistent)
#define OFF_W2HI 34816                // 4352  (persistent)
#define OFF_BE1  39168                // 512
#define OFF_BE2  39680                // 64
#define OFF_S0   39744                // stage buf 0: A(8x272) + B(16x272) = 6528
#define OFF_S1   46272                // stage buf 1
#define K3_SMEM  52800

#define K3_GRID  444                  // 148 SM x 3 CTAs, one wave
#define N_TILES  (72*BATCH)

__device__ __forceinline__ void k3_tdec(int tt, int& b, int& i0, int& j0){
    int tri = tt % 72; b = tt / 72;
    int jt = 0;
#pragma unroll
    for (int q=1;q<8;q++) if (tri >= q*(q+1)) jt = q;
    int it = tri - jt*(jt+1);
    i0 = it*8; j0 = jt*16;
}

__device__ __forceinline__ void k3_stage(uint32_t sbase, int b, int i0, int j0, int tid){
    if (tid < 128){
        int rr = tid >> 4, c16 = tid & 15;
        cp16(sbase + rr*272 + c16*16,
             g_A0h + ((size_t)(b*NN + i0 + rr))*128 + c16*8);
    } else {
        int l = tid - 128;
#pragma unroll
        for (int h2_ = 0; h2_ < 2; h2_++){
            int idx = l + h2_*128;
            int rr = idx >> 4, c16 = idx & 15;
            cp16(sbase + 2176 + rr*272 + c16*16,
                 g_B0h + ((size_t)(b*NN + j0 + rr))*128 + c16*8);
        }
    }
}

__global__ void __launch_bounds__(256, 3)
k3_edge_mma(const float* __restrict__ be1,
            const float* __restrict__ be2,
            float* __restrict__ U)
{
    extern __shared__ char smem[];
    float* smemf = reinterpret_cast<float*>(smem);
    const uint32_t sb = smem_u32(smem);
    const int tid = threadIdx.x;
    const int w = tid >> 5;          // warp 0..7 -> pair rows w*16..+15
    const int lane = tid & 31;
    const int g = lane >> 2;
    const int r = lane & 3;

    // ---- stage persistent weights once ----
    {
        const uint4* sh  = reinterpret_cast<const uint4*>(g_Bhi);
        uint4* dh = reinterpret_cast<uint4*>(smem + OFF_BHI);
        for (int l = tid; l < 2176; l += 256) dh[l] = sh[l];
        const uint4* s2h = reinterpret_cast<const uint4*>(g_W2hi);
        uint4* d2h = reinterpret_cast<uint4*>(smem + OFF_W2HI);
        for (int l = tid; l < 272; l += 256) d2h[l] = s2h[l];
        if (tid < 128) smemf[OFF_BE1/4 + tid] = be1[tid];
        else if (tid < 144) smemf[OFF_BE2/4 + tid - 128] = be2[tid - 128];
    }

    const uint32_t bOff = (uint32_t)(((((lane >> 4) << 3) + (lane & 7))*272)
                                    + ((lane >> 3) & 1)*16);
    const uint32_t bHi = sb + OFF_BHI + bOff;
    const uint32_t wHi = sb + OFF_W2HI + bOff;
    const __half2 slope = __floats2half2_rn(0.1f, 0.1f);

    // ---- prologue: stage first tile into buf0 ----
    int tt = blockIdx.x;
    if (tt < N_TILES){
        int b0_, pi0, pj0;
        k3_tdec(tt, b0_, pi0, pj0);
        k3_stage(sb + OFF_S0, b0_, pi0, pj0, tid);
    }
    CP_COMMIT();

    int cur = 0;
    for (; tt < N_TILES; tt += K3_GRID){
        int b, i0, j0;
        k3_tdec(tt, b, i0, j0);

        CP_WAIT0();
        __syncthreads();

        // issue next tile's loads into the other buffer
        const int nt = tt + K3_GRID;
        if (nt < N_TILES){
            int nb, ni0, nj0;
            k3_tdec(nt, nb, ni0, nj0);
            k3_stage(sb + (cur ? OFF_S0 : OFF_S1), nb, ni0, nj0, tid);
        }
        CP_COMMIT();

        const uint32_t sA = cur ? OFF_S1 : OFF_S0;
        const __half2* pA  = reinterpret_cast<const __half2*>(smem + sA) + w*68;
        const __half2* pB0 = reinterpret_cast<const __half2*>(smem + sA + 2176) + g*68;
        const __half2* pB1 = pB0 + 8*68;

        float e[2][4];
#pragma unroll
        for (int a2=0;a2<2;a2++)
#pragma unroll
            for (int a3=0;a3<4;a3++) e[a2][a3] = 0.f;

        // ---- two column passes: GEMM1 (64 cols) chained into GEMM2 ----
#pragma unroll
        for (int pass = 0; pass < 2; pass++){
            float acc[8][4];
#pragma unroll
            for (int a2=0;a2<8;a2++)
#pragma unroll
                for (int a3=0;a3<4;a3++) acc[a2][a3] = 0.f;

#pragma unroll
            for (int ks = 0; ks < 8; ks++){
                __half2 aa  = pA[ks*8 + r];
                __half2 ab  = pA[ks*8 + 4 + r];
                __half2 b0a = pB0[ks*8 + r];
                __half2 b0b = pB0[ks*8 + 4 + r];
                __half2 b1a = pB1[ks*8 + r];
                __half2 b1b = pB1[ks*8 + 4 + r];

                uint32_t ah[4];
                ah[0] = lrelu2(__hadd2(aa, b0a), slope);
                ah[1] = lrelu2(__hadd2(aa, b1a), slope);
                ah[2] = lrelu2(__hadd2(ab, b0b), slope);
                ah[3] = lrelu2(__hadd2(ab, b1b), slope);

#pragma unroll
                for (int n2 = 0; n2 < 4; n2++){
                    uint32_t bh[4];
                    LDM4(bh, bHi + (pass*4 + n2)*4352 + ks*32);
                    MMA16816H(acc[2*n2],   ah, bh[0], bh[1]);
                    MMA16816H(acc[2*n2+1], ah, bh[2], bh[3]);
                }
            }

            // GEMM2 for this pass's t1 columns (qk = pass*4 .. pass*4+3)
#pragma unroll
            for (int q2 = 0; q2 < 4; q2++){
                const int qk = pass*4 + q2;
                uint32_t bh[4];
                LDM4(bh, wHi + qk*32);
                const int cA = qk*16 + 2*r;
                const int cB = qk*16 + 8 + 2*r;
                float beA0 = smemf[OFF_BE1/4 + cA], beA1 = smemf[OFF_BE1/4 + cA + 1];
                float beB0 = smemf[OFF_BE1/4 + cB], beB1 = smemf[OFF_BE1/4 + cB + 1];
                uint32_t ah[4];
                ah[0] = packh2(lrelu(acc[2*q2][0]+beA0),   lrelu(acc[2*q2][1]+beA1));
                ah[1] = packh2(lrelu(acc[2*q2][2]+beA0),   lrelu(acc[2*q2][3]+beA1));
                ah[2] = packh2(lrelu(acc[2*q2+1][0]+beB0), lrelu(acc[2*q2+1][1]+beB1));
                ah[3] = packh2(lrelu(acc[2*q2+1][2]+beB0), lrelu(acc[2*q2+1][3]+beB1));
                MMA16816H(e[0], ah, bh[0], bh[1]);
                MMA16816H(e[1], ah, bh[2], bh[3]);
            }
        }

        // ---- direct scatter into U ----
        {
            const int i = i0 + w;
            float* Ub = U + (size_t)b*U_PER_B;
#pragma unroll
            for (int rh = 0; rh < 2; rh++){
                const int j = j0 + g + rh*8;
                if (i < j){
#pragma unroll
                    for (int t_ = 0; t_ < 2; t_++){
                        const int c = t_*8 + 2*r;
                        float vx = e[t_][rh*2+0] + smemf[OFF_BE2/4 + c];
                        float vy = e[t_][rh*2+1] + smemf[OFF_BE2/4 + c + 1];
                        const int qq = c >> 2, m = c & 3;
                        float2 v2 = make_float2(vx, vy);
                        *reinterpret_cast<float2*>(Ub + (size_t)(4*i+qq)*U_STRIDE + 4*j + m) = v2;
                        *reinterpret_cast<float2*>(Ub + (size_t)(4*j+qq)*U_STRIDE + 4*i + m) = v2;
                    }
                }
            }
        }
        cur ^= 1;
    }
}

// ---------------------------------------------------------------------------
extern "C" void kernel_launch(void* const* d_in, const int* in_sizes, int n_in,
                              void* d_out, int out_size)
{
    const float* x   = (const float*)d_in[0];
    const float* Wg0 = (const float*)d_in[4];
    const float* bg0 = (const float*)d_in[5];
    const float* Wg1 = (const float*)d_in[6];
    const float* bg1 = (const float*)d_in[7];
    const float* Wg2 = (const float*)d_in[8];
    const float* bg2 = (const float*)d_in[9];
    const float* Wn0 = (const float*)d_in[10];
    const float* bn0 = (const float*)d_in[11];
    const float* Wn1 = (const float*)d_in[12];
    const float* bn1 = (const float*)d_in[13];
    const float* Wn2 = (const float*)d_in[14];
    const float* bn2 = (const float*)d_in[15];
    const float* We0 = (const float*)d_in[16];
    const float* be0 = (const float*)d_in[17];
    const float* We1 = (const float*)d_in[18];
    const float* be1 = (const float*)d_in[19];
    const float* We2 = (const float*)d_in[20];
    const float* be2 = (const float*)d_in[21];

    float* h_out = (float*)d_out;                 // (16384, 64)
    float* U     = h_out + (size_t)TOTAL*D_MP;    // (128, 512, 512)

    static bool init_done = false;
    static cudaStream_t s2;
    static cudaEvent_t ev_fork, ev_join;
    if (!init_done){
        cudaFuncSetAttribute(k3_edge_mma, cudaFuncAttributeMaxDynamicSharedMemorySize, K3_SMEM);
        cudaFuncSetAttribute(k2b_node, cudaFuncAttributeMaxDynamicSharedMemorySize, K2B_SMEM);
        cudaStreamCreateWithFlags(&s2, cudaStreamNonBlocking);
        cudaEventCreateWithFlags(&ev_fork, cudaEventDisableTiming);
        cudaEventCreateWithFlags(&ev_join, cudaEventDisableTiming);
        init_done = true;
    }

    // main stream: k1 -> k2_ab -> k3 ; side stream: k2b (forks after k1)
    k1_fused<<<164, 512>>>(x, Wg0,bg0, Wg1,bg1, Wg2,bg2, We1, We2, h_out);
    cudaEventRecord(ev_fork, 0);
    cudaStreamWaitEvent(s2, ev_fork, 0);
    k2b_node<<<512, 256, K2B_SMEM, s2>>>(h_out, Wn0,bn0, Wn1,bn1, Wn2,bn2, U);
    cudaEventRecord(ev_join, s2);
    k2_ab<<<512, 256>>>(h_out, We0, be0);
    k3_edge_mma<<<K3_GRID, 256, K3_SMEM>>>(be1, be2, U);
    cudaStreamWaitEvent(0, ev_join, 0);
}